// round 14
// baseline (speedup 1.0000x reference)
#include <cuda_runtime.h>
#include <cuda_bf16.h>

// Scratch (no cudaMalloc). Shapes: B=1024 (<=4096), E=50000 (<=65536).
__device__ float g_hr[4096];            // hr_part[b] + bias
__device__ float g_tail[65536];         // tail_part[e]
__device__ unsigned g_launch_ctr = 0;   // CTA tickets -> per-launch epoch
__device__ unsigned g_hr_cnt = 0;       // monotonic: +B per launch
__device__ unsigned g_chunk_cnt[64];    // monotonic: +chunk_size per launch

#define THREADS 256
#define BTILE   16
#define CHUNK   1024   // tail rows per readiness chunk (64 chunks max)

// ---------------------------------------------------------------------------
// Fused pipelined kernel (C==512, B%16==0, E%4==0 fast path).
// Phase 1: warp-per-row dots (grid-stride), flagging chunk completion.
// Phase 2: bcast stores, consuming chunks as they become ready.
// All CTAs co-resident (grid sized by occupancy) -> no deadlock.
// ---------------------------------------------------------------------------
__global__ __launch_bounds__(THREADS)
void fused512_kernel(const float* __restrict__ hr,
                     const float* __restrict__ tail,
                     const float* __restrict__ W,    // [1024]: W1 | W2
                     const float* __restrict__ bias,
                     int B, int E,
                     float* __restrict__ out,
                     long long zstart, long long total,
                     int nblocks) {
    const int tid   = threadIdx.x;
    const int gid   = blockIdx.x * THREADS + tid;
    const int gsz   = nblocks * THREADS;
    const int lane  = tid & 31;
    const int gwarp = gid >> 5;
    const int nwarps = gsz >> 5;

    // Per-launch epoch (replay-safe): all CTAs of one launch get same value.
    __shared__ unsigned s_epoch;
    if (tid == 0)
        s_epoch = atomicAdd(&g_launch_ctr, 1u) / (unsigned)nblocks;
    __syncthreads();
    const unsigned epoch = s_epoch;

    // Trailing zero-fill (reference returns (scores, 0)).
    for (long long zi = zstart + gid; zi < total; zi += gsz)
        out[zi] = 0.0f;

    // ---------------- Phase 1: dots ----------------
    const int rows = B + E;
    const float bv = __ldg(bias);
    const float4* w1 = reinterpret_cast<const float4*>(W);
    const float4* w2 = reinterpret_cast<const float4*>(W + 512);

    for (int r = gwarp; r < rows; r += nwarps) {
        const float4* r4;
        const float4* w4;
        if (r < B) { r4 = reinterpret_cast<const float4*>(hr + (size_t)r * 512);        w4 = w1; }
        else       { r4 = reinterpret_cast<const float4*>(tail + (size_t)(r - B) * 512); w4 = w2; }

        float4 a0 = __ldg(r4 + lane);
        float4 a1 = __ldg(r4 + lane + 32);
        float4 a2 = __ldg(r4 + lane + 64);
        float4 a3 = __ldg(r4 + lane + 96);
        float4 b0 = __ldg(w4 + lane);
        float4 b1 = __ldg(w4 + lane + 32);
        float4 b2 = __ldg(w4 + lane + 64);
        float4 b3 = __ldg(w4 + lane + 96);
        float s0 = a0.x * b0.x + a0.y * b0.y + a0.z * b0.z + a0.w * b0.w;
        float s1 = a1.x * b1.x + a1.y * b1.y + a1.z * b1.z + a1.w * b1.w;
        float s2 = a2.x * b2.x + a2.y * b2.y + a2.z * b2.z + a2.w * b2.w;
        float s3 = a3.x * b3.x + a3.y * b3.y + a3.z * b3.z + a3.w * b3.w;
        float acc = (s0 + s1) + (s2 + s3);
#pragma unroll
        for (int off = 16; off; off >>= 1)
            acc += __shfl_xor_sync(0xffffffffu, acc, off);

        if (lane == 0) {
            if (r < B) {
                g_hr[r] = acc + bv;
                __threadfence();
                atomicAdd(&g_hr_cnt, 1u);
            } else {
                int t_idx = r - B;
                g_tail[t_idx] = acc;
                __threadfence();
                atomicAdd(&g_chunk_cnt[t_idx >> 10], 1u);
            }
        }
    }

    // Wait for all hr rows (tiny; done very early).
    if (tid == 0) {
        unsigned tgt = (epoch + 1u) * (unsigned)B;
        while (*((volatile unsigned*)&g_hr_cnt) < tgt)
            __nanosleep(64);
    }
    __syncthreads();
    __threadfence();

    // ---------------- Phase 2: broadcast stores ----------------
    const int E4  = E >> 2;
    const int nbt = B / BTILE;
    const long long items = (long long)nbt * E4;
    const long long rs4 = (long long)E4;
    const float4* gt4 = reinterpret_cast<const float4*>(g_tail);
    float4* out4 = reinterpret_cast<float4*>(out);

    int last_c = -1;
    for (long long it = gid; it < items; it += gsz) {
        int bt = (int)(it / E4);
        int e4 = (int)(it - (long long)bt * E4);

        int c = e4 >> 8;                 // chunk = (e4*4)/1024
        if (c != last_c) {
            int size_c = E - c * CHUNK;
            if (size_c > CHUNK) size_c = CHUNK;
            unsigned tgt = (epoch + 1u) * (unsigned)size_c;
            while (*((volatile unsigned*)&g_chunk_cnt[c]) < tgt)
                __nanosleep(32);
            __threadfence();
            last_c = c;
        }

        float4 t = __ldcg(gt4 + e4);     // L2 path: never-stale
        int b0 = bt * BTILE;
        float4* base = out4 + (long long)b0 * rs4 + e4;
#pragma unroll
        for (int i = 0; i < BTILE; i++) {
            float h = __ldcg(&g_hr[b0 + i]);
            float4 r = make_float4(t.x + h, t.y + h, t.z + h, t.w + h);
            __stcs(base + (long long)i * rs4, r);
        }
    }
}

// ---------------------------------------------------------------------------
// Generic fallback (odd shapes): dots over B+E rows, then bcast.
// ---------------------------------------------------------------------------
__global__ void dots_kernel(const float* __restrict__ hr,
                            const float* __restrict__ tail,
                            const float* __restrict__ W,
                            const float* __restrict__ bias,
                            int B, int E, int C,
                            float* __restrict__ out,
                            long long zstart, long long total) {
    int gid  = blockIdx.x * blockDim.x + threadIdx.x;
    int warp = gid >> 5;
    int lane = threadIdx.x & 31;
    long long zi = zstart + (long long)gid;
    if (zi < total) out[zi] = 0.0f;
    if (warp >= B + E) return;
    const float* row; const float* w;
    if (warp < B) { row = hr   + (size_t)warp * C;       w = W;     }
    else          { row = tail + (size_t)(warp - B) * C; w = W + C; }
    float acc = 0.0f;
    for (int k = lane; k < C; k += 32)
        acc += __ldg(row + k) * __ldg(w + k);
#pragma unroll
    for (int off = 16; off; off >>= 1)
        acc += __shfl_xor_sync(0xffffffffu, acc, off);
    if (lane == 0) {
        if (warp < B) g_hr[warp] = acc + bias[0];
        else          g_tail[warp - B] = acc;
    }
}

__global__ void bcast_scalar_kernel(float* __restrict__ out, int E) {
    int e = blockIdx.x * blockDim.x + threadIdx.x;
    if (e >= E) return;
    int b = blockIdx.y;
    out[(size_t)b * E + e] = g_hr[b] + g_tail[e];
}

extern "C" void kernel_launch(void* const* d_in, const int* in_sizes, int n_in,
                              void* d_out, int out_size) {
    const float* hr   = (const float*)d_in[0];  // [B, C]
    const float* tail = (const float*)d_in[1];  // [E, C]
    const float* W    = (const float*)d_in[2];  // [1, 2C]
    const float* bias = (const float*)d_in[3];  // [1]
    float* out = (float*)d_out;

    int C = in_sizes[2] / 2;
    int B = in_sizes[0] / C;
    int E = in_sizes[1] / C;

    long long BE    = (long long)B * (long long)E;
    long long total = (long long)out_size;

    bool fast = (C == 512) && ((E & 3) == 0) && ((B & (BTILE - 1)) == 0) &&
                (B <= 4096) && (E <= 64 * CHUNK);

    if (fast) {
        int sm_count = 0;
        cudaDeviceGetAttribute(&sm_count, cudaDevAttrMultiProcessorCount, 0);
        if (sm_count <= 0) sm_count = 148;
        int max_blk = 0;
        cudaOccupancyMaxActiveBlocksPerMultiprocessor(
            &max_blk, fused512_kernel, THREADS, 0);
        if (max_blk <= 0) max_blk = 1;
        int nblocks = sm_count * max_blk;   // guaranteed co-resident
        fused512_kernel<<<nblocks, THREADS>>>(hr, tail, W, bias, B, E,
                                              out, BE, total, nblocks);
    } else {
        {
            int rows = B + E;
            long long lanes = (long long)rows * 32;
            long long extra = (total > BE) ? (total - BE) : 0;
            if (extra > lanes) lanes = extra;
            int blocks = (int)((lanes + THREADS - 1) / THREADS);
            dots_kernel<<<blocks, THREADS>>>(hr, tail, W, bias, B, E, C,
                                             out, BE, total);
        }
        {
            dim3 grid((E + THREADS - 1) / THREADS, B);
            bcast_scalar_kernel<<<grid, THREADS>>>(out, E);
        }
    }
}

// round 15
// speedup vs baseline: 1.7084x; 1.7084x over previous
#include <cuda_runtime.h>
#include <cuda_bf16.h>

// Scratch (no cudaMalloc). Shapes: B=1024 (<=4096), E=50000.
__device__ float g_hr[4096];      // hr_part[b] + bias

#define THREADS 256
#define ETILE   32    // e-columns per fused CTA (8 float4)

// ---------------------------------------------------------------------------
// Kernel 1 (tiny): hr_part[b] = hr[b,:].W1 + bias (warp per row, batched
// loads) + trailing zero-fill. Ends with PDL trigger.
// ---------------------------------------------------------------------------
__global__ void hr_dots_kernel(const float* __restrict__ hr,
                               const float* __restrict__ W,
                               const float* __restrict__ bias,
                               int B,
                               float* __restrict__ out,
                               long long zstart, long long total) {
    int gid  = blockIdx.x * blockDim.x + threadIdx.x;
    int warp = gid >> 5;
    int lane = threadIdx.x & 31;

    long long zi = zstart + (long long)gid;
    if (zi < total) out[zi] = 0.0f;

    if (warp < B) {
        const float4* r4 = reinterpret_cast<const float4*>(hr + (size_t)warp * 512);
        const float4* w4 = reinterpret_cast<const float4*>(W);
        float4 a0 = __ldg(r4 + lane);
        float4 a1 = __ldg(r4 + lane + 32);
        float4 a2 = __ldg(r4 + lane + 64);
        float4 a3 = __ldg(r4 + lane + 96);
        float4 b0 = __ldg(w4 + lane);
        float4 b1 = __ldg(w4 + lane + 32);
        float4 b2 = __ldg(w4 + lane + 64);
        float4 b3 = __ldg(w4 + lane + 96);
        float s0 = a0.x * b0.x + a0.y * b0.y + a0.z * b0.z + a0.w * b0.w;
        float s1 = a1.x * b1.x + a1.y * b1.y + a1.z * b1.z + a1.w * b1.w;
        float s2 = a2.x * b2.x + a2.y * b2.y + a2.z * b2.z + a2.w * b2.w;
        float s3 = a3.x * b3.x + a3.y * b3.y + a3.z * b3.z + a3.w * b3.w;
        float acc = (s0 + s1) + (s2 + s3);
#pragma unroll
        for (int off = 16; off; off >>= 1)
            acc += __shfl_xor_sync(0xffffffffu, acc, off);
        if (lane == 0) g_hr[warp] = acc + bias[0];
    }
    cudaTriggerProgrammaticLaunchCompletion();
}

// ---------------------------------------------------------------------------
// Kernel 2 (fused, C==512): per CTA, compute ETILE tail dots into SMEM
// (reads), then write those e-columns for all B rows (stores). CTA-local
// dependency only; read/store phases of different CTAs overlap on the LTS
// pipe. g_hr consumed after phase 1 via PDL sync (hr kernel fully hidden).
// ---------------------------------------------------------------------------
__global__ __launch_bounds__(THREADS)
void fused_tail_bcast_kernel(const float* __restrict__ tail,
                             const float* __restrict__ W2,  // W + 512
                             float* __restrict__ out,
                             int B, int E) {
    __shared__ float sh_t[ETILE];
    __shared__ float sh_h[4096];

    const int tid = threadIdx.x;
    const int w   = tid >> 5;
    const int l   = tid & 31;
    const int e0  = blockIdx.x * ETILE;

    // ---- Phase 1: 32 tail dots (warp w handles rows e0+w, +8, +16, +24) ----
    const float4* w4 = reinterpret_cast<const float4*>(W2);
    float4 b0 = __ldg(w4 + l);
    float4 b1 = __ldg(w4 + l + 32);
    float4 b2 = __ldg(w4 + l + 64);
    float4 b3 = __ldg(w4 + l + 96);

#pragma unroll
    for (int j = 0; j < ETILE / 8; j++) {
        int r = w + j * 8;
        int e = e0 + r;
        if (e < E) {
            const float4* r4 =
                reinterpret_cast<const float4*>(tail + (size_t)e * 512);
            float4 a0 = __ldg(r4 + l);
            float4 a1 = __ldg(r4 + l + 32);
            float4 a2 = __ldg(r4 + l + 64);
            float4 a3 = __ldg(r4 + l + 96);
            float s0 = a0.x * b0.x + a0.y * b0.y + a0.z * b0.z + a0.w * b0.w;
            float s1 = a1.x * b1.x + a1.y * b1.y + a1.z * b1.z + a1.w * b1.w;
            float s2 = a2.x * b2.x + a2.y * b2.y + a2.z * b2.z + a2.w * b2.w;
            float s3 = a3.x * b3.x + a3.y * b3.y + a3.z * b3.z + a3.w * b3.w;
            float acc = (s0 + s1) + (s2 + s3);
#pragma unroll
            for (int off = 16; off; off >>= 1)
                acc += __shfl_xor_sync(0xffffffffu, acc, off);
            if (l == 0) sh_t[r] = acc;
        }
    }

    // ---- hr results: produced by the (long-since-finished) hr kernel ----
    cudaGridDependencySynchronize();
    for (int b = tid; b < B; b += THREADS)
        sh_h[b] = g_hr[b];
    __syncthreads();

    // ---- Phase 2: store. Thread owns float4 col (tid&7), rows tid>>3+32k. ----
    const int col = tid & 7;                 // 0..7 float4 cols in tile
    const int e4  = (e0 >> 2) + col;
    const int E4  = E >> 2;
    if (e4 >= E4) return;

    float4 t = *reinterpret_cast<const float4*>(sh_t + col * 4);
    float4* out4 = reinterpret_cast<float4*>(out);
    const long long rs4 = (long long)E4;

    int b = tid >> 3;                        // 0..31
#pragma unroll 8
    for (; b < B; b += 32) {
        float h = sh_h[b];
        float4 r = make_float4(t.x + h, t.y + h, t.z + h, t.w + h);
        __stcs(out4 + (long long)b * rs4 + e4, r);
    }
}

// ---------------------------------------------------------------------------
// Generic fallback (odd shapes): dots over B+E rows, then scalar broadcast.
// ---------------------------------------------------------------------------
__device__ float g_tail_fb[65536];

__global__ void dots_kernel(const float* __restrict__ hr,
                            const float* __restrict__ tail,
                            const float* __restrict__ W,
                            const float* __restrict__ bias,
                            int B, int E, int C,
                            float* __restrict__ out,
                            long long zstart, long long total) {
    int gid  = blockIdx.x * blockDim.x + threadIdx.x;
    int warp = gid >> 5;
    int lane = threadIdx.x & 31;
    long long zi = zstart + (long long)gid;
    if (zi < total) out[zi] = 0.0f;
    if (warp >= B + E) return;
    const float* row; const float* w;
    if (warp < B) { row = hr   + (size_t)warp * C;       w = W;     }
    else          { row = tail + (size_t)(warp - B) * C; w = W + C; }
    float acc = 0.0f;
    for (int k = lane; k < C; k += 32)
        acc += __ldg(row + k) * __ldg(w + k);
#pragma unroll
    for (int off = 16; off; off >>= 1)
        acc += __shfl_xor_sync(0xffffffffu, acc, off);
    if (lane == 0) {
        if (warp < B) g_hr[warp] = acc + bias[0];
        else          g_tail_fb[warp - B] = acc;
    }
}

__global__ void bcast_scalar_kernel(float* __restrict__ out, int E) {
    int e = blockIdx.x * blockDim.x + threadIdx.x;
    if (e >= E) return;
    int b = blockIdx.y;
    out[(size_t)b * E + e] = g_hr[b] + g_tail_fb[e];
}

extern "C" void kernel_launch(void* const* d_in, const int* in_sizes, int n_in,
                              void* d_out, int out_size) {
    const float* hr   = (const float*)d_in[0];  // [B, C]
    const float* tail = (const float*)d_in[1];  // [E, C]
    const float* W    = (const float*)d_in[2];  // [1, 2C]
    const float* bias = (const float*)d_in[3];  // [1]
    float* out = (float*)d_out;

    int C = in_sizes[2] / 2;
    int B = in_sizes[0] / C;
    int E = in_sizes[1] / C;

    long long BE    = (long long)B * (long long)E;
    long long total = (long long)out_size;

    bool fast = (C == 512) && ((E & 3) == 0) && (B <= 4096) && ((B & 31) == 0);

    if (fast) {
        // 1) hr dots + zero-fill (tiny), PDL-triggering
        {
            long long lanes = (long long)B * 32;
            long long extra = (total > BE) ? (total - BE) : 0;
            if (extra > lanes) lanes = extra;
            int blocks = (int)((lanes + THREADS - 1) / THREADS);
            hr_dots_kernel<<<blocks, THREADS>>>(hr, W, bias, B, out, BE, total);
        }
        // 2) fused tail dots + broadcast (PDL overlap with kernel 1)
        {
            int blocks = (E + ETILE - 1) / ETILE;
            cudaLaunchConfig_t cfg = {};
            cfg.gridDim  = dim3(blocks, 1, 1);
            cfg.blockDim = dim3(THREADS, 1, 1);
            cudaLaunchAttribute attrs[1];
            attrs[0].id = cudaLaunchAttributeProgrammaticStreamSerialization;
            attrs[0].val.programmaticStreamSerializationAllowed = 1;
            cfg.attrs = attrs;
            cfg.numAttrs = 1;
            cudaLaunchKernelEx(&cfg, fused_tail_bcast_kernel,
                               tail, W + C, out, B, E);
        }
    } else {
        {
            int rows = B + E;
            long long lanes = (long long)rows * 32;
            long long extra = (total > BE) ? (total - BE) : 0;
            if (extra > lanes) lanes = extra;
            int blocks = (int)((lanes + THREADS - 1) / THREADS);
            dots_kernel<<<blocks, THREADS>>>(hr, tail, W, bias, B, E, C,
                                             out, BE, total);
        }
        {
            dim3 grid((E + THREADS - 1) / THREADS, B);
            bcast_scalar_kernel<<<grid, THREADS>>>(out, E);
        }
    }
}

// round 16
// speedup vs baseline: 1.8386x; 1.0762x over previous
#include <cuda_runtime.h>
#include <cuda_bf16.h>
#include <cuda_pipeline.h>

// Scratch (no cudaMalloc). Shapes: B=1024 (<=4096), E=50000 (<=65536).
__device__ float g_hr[4096];      // hr_part[b] + bias
__device__ float g_tail[65536];   // tail_part[e]

#define THREADS 256
#define NW      8      // warps per CTA
#define RING    4      // smem row slots per warp (2KB each)
#define DEPTH   3      // outstanding cp.async row groups per warp
#define BTILE   16     // frozen bcast config (31.1us = LTS wall)

#define DOTS_SMEM (NW * RING * 128 * 16)   // 64 KB dynamic

// ---------------------------------------------------------------------------
// Dots via cp.async pipeline (C==512 fast path). Warp-per-row, but each warp
// keeps DEPTH rows in flight through an async smem ring -> read stream is
// MLP-unbound and saturates the LTS cap instead of 8-LDG register MLP.
// Also zero-fills trailing output. Ends with PDL trigger.
// ---------------------------------------------------------------------------
__global__ __launch_bounds__(THREADS)
void dots_async_kernel(const float* __restrict__ hr,
                       const float* __restrict__ tail,
                       const float* __restrict__ W,    // [1024]: W1 | W2
                       const float* __restrict__ bias,
                       int B, int E,
                       float* __restrict__ out,
                       long long zstart, long long total,
                       int nblocks) {
    extern __shared__ float4 sbuf[];   // [NW][RING][128]

    const int tid  = threadIdx.x;
    const int w    = tid >> 5;
    const int l    = tid & 31;
    const int gid  = blockIdx.x * THREADS + tid;
    const int gsz  = nblocks * THREADS;
    const int gwarp  = blockIdx.x * NW + w;
    const int nwarps = nblocks * NW;

    // Trailing zero-fill (reference returns (scores, 0)).
    for (long long zi = zstart + gid; zi < total; zi += gsz)
        out[zi] = 0.0f;

    const int rows = B + E;
    const float bv = __ldg(bias);

    // W1 and W2 lane-slices in registers (reused for every row).
    const float4* w1 = reinterpret_cast<const float4*>(W);
    const float4* w2 = reinterpret_cast<const float4*>(W + 512);
    float4 u0 = __ldg(w1 + l), u1 = __ldg(w1 + l + 32),
           u2 = __ldg(w1 + l + 64), u3 = __ldg(w1 + l + 96);
    float4 v0 = __ldg(w2 + l), v1 = __ldg(w2 + l + 32),
           v2 = __ldg(w2 + l + 64), v3 = __ldg(w2 + l + 96);

    // Rows this warp owns: r = gwarp + k*nwarps, k = 0..nrows-1.
    int nrows = 0;
    if (gwarp < rows) nrows = (rows - gwarp + nwarps - 1) / nwarps;

    float4* wbuf = sbuf + (size_t)w * (RING * 128);

    // Issue row k's 2KB into ring slot k&3 (4 x 16B per lane), or an empty
    // commit group past the end (completes immediately, keeps counts const).
    auto issue_row = [&](int k) {
        if (k < nrows) {
            int r = gwarp + k * nwarps;
            const float4* src = (r < B)
                ? reinterpret_cast<const float4*>(hr + (size_t)r * 512)
                : reinterpret_cast<const float4*>(tail + (size_t)(r - B) * 512);
            float4* dst = wbuf + (k & (RING - 1)) * 128;
            __pipeline_memcpy_async(dst + l,      src + l,      16);
            __pipeline_memcpy_async(dst + l + 32, src + l + 32, 16);
            __pipeline_memcpy_async(dst + l + 64, src + l + 64, 16);
            __pipeline_memcpy_async(dst + l + 96, src + l + 96, 16);
        }
        __pipeline_commit();
    };

#pragma unroll
    for (int d = 0; d < DEPTH; d++) issue_row(d);

    for (int k = 0; k < nrows; k++) {
        __pipeline_wait_prior(DEPTH - 1);   // oldest group complete
        const float4* bp = wbuf + (k & (RING - 1)) * 128;
        float4 a0 = bp[l];
        float4 a1 = bp[l + 32];
        float4 a2 = bp[l + 64];
        float4 a3 = bp[l + 96];
        // Refill the ring ASAP (slot (k+DEPTH)&3 != k&3 for RING=4,DEPTH=3).
        issue_row(k + DEPTH);

        int r = gwarp + k * nwarps;
        float4 b0, b1, b2, b3;
        if (r < B) { b0 = u0; b1 = u1; b2 = u2; b3 = u3; }
        else       { b0 = v0; b1 = v1; b2 = v2; b3 = v3; }
        float s0 = a0.x * b0.x + a0.y * b0.y + a0.z * b0.z + a0.w * b0.w;
        float s1 = a1.x * b1.x + a1.y * b1.y + a1.z * b1.z + a1.w * b1.w;
        float s2 = a2.x * b2.x + a2.y * b2.y + a2.z * b2.z + a2.w * b2.w;
        float s3 = a3.x * b3.x + a3.y * b3.y + a3.z * b3.z + a3.w * b3.w;
        float acc = (s0 + s1) + (s2 + s3);
#pragma unroll
        for (int off = 16; off; off >>= 1)
            acc += __shfl_xor_sync(0xffffffffu, acc, off);
        if (l == 0) {
            if (r < B) g_hr[r] = acc + bv;
            else       g_tail[r - B] = acc;
        }
    }

    cudaTriggerProgrammaticLaunchCompletion();
}

// ---------------------------------------------------------------------------
// Generic dots fallback (any C): warp per row over B+E rows.
// ---------------------------------------------------------------------------
__global__ void dots_kernel(const float* __restrict__ hr,
                            const float* __restrict__ tail,
                            const float* __restrict__ W,
                            const float* __restrict__ bias,
                            int B, int E, int C,
                            float* __restrict__ out,
                            long long zstart, long long total) {
    int gid  = blockIdx.x * blockDim.x + threadIdx.x;
    int warp = gid >> 5;
    int lane = threadIdx.x & 31;
    long long zi = zstart + (long long)gid;
    if (zi < total) out[zi] = 0.0f;
    if (warp >= B + E) return;
    const float* row; const float* w;
    if (warp < B) { row = hr   + (size_t)warp * C;       w = W;     }
    else          { row = tail + (size_t)(warp - B) * C; w = W + C; }
    float acc = 0.0f;
    for (int k = lane; k < C; k += 32)
        acc += __ldg(row + k) * __ldg(w + k);
#pragma unroll
    for (int off = 16; off; off >>= 1)
        acc += __shfl_xor_sync(0xffffffffu, acc, off);
    if (lane == 0) {
        if (warp < B) g_hr[warp] = acc + bias[0];
        else          g_tail[warp - B] = acc;
    }
}

// ---------------------------------------------------------------------------
// Broadcast write, b-tiled (FROZEN R12 config: 31.1us = LTS wall). PDL-aware.
// ---------------------------------------------------------------------------
__global__ __launch_bounds__(THREADS)
void bcast_vec_kernel(float* __restrict__ out, int E4, long long E, int B) {
    __shared__ float sh[BTILE];
    int b0 = blockIdx.y * BTILE;
    int e4 = blockIdx.x * blockDim.x + threadIdx.x;
    float4* base = reinterpret_cast<float4*>(out + (size_t)b0 * E) + e4;
    long long rowstride4 = E >> 2;
    int nb = B - b0;

    cudaGridDependencySynchronize();

    if (threadIdx.x < BTILE) {
        int b = b0 + threadIdx.x;
        sh[threadIdx.x] = (b < B) ? g_hr[b] : 0.0f;
    }
    __syncthreads();

    if (e4 >= E4) return;

    float4 t = __ldg(reinterpret_cast<const float4*>(g_tail) + e4);

    if (nb >= BTILE) {
#pragma unroll
        for (int i = 0; i < BTILE; i++) {
            float h = sh[i];
            float4 r = make_float4(t.x + h, t.y + h, t.z + h, t.w + h);
            __stcs(base + (long long)i * rowstride4, r);
        }
    } else {
        for (int i = 0; i < nb; i++) {
            float h = sh[i];
            float4 r = make_float4(t.x + h, t.y + h, t.z + h, t.w + h);
            __stcs(base + (long long)i * rowstride4, r);
        }
    }
}

// Scalar fallback for E % 4 != 0.
__global__ void bcast_scalar_kernel(float* __restrict__ out, int E) {
    int e = blockIdx.x * blockDim.x + threadIdx.x;
    if (e >= E) return;
    int b = blockIdx.y;
    out[(size_t)b * E + e] = g_hr[b] + g_tail[e];
}

extern "C" void kernel_launch(void* const* d_in, const int* in_sizes, int n_in,
                              void* d_out, int out_size) {
    const float* hr   = (const float*)d_in[0];  // [B, C]
    const float* tail = (const float*)d_in[1];  // [E, C]
    const float* W    = (const float*)d_in[2];  // [1, 2C]
    const float* bias = (const float*)d_in[3];  // [1]
    float* out = (float*)d_out;

    int C = in_sizes[2] / 2;
    int B = in_sizes[0] / C;
    int E = in_sizes[1] / C;

    long long BE    = (long long)B * (long long)E;
    long long total = (long long)out_size;

    bool fast = (C == 512) && (B <= 4096) && (E <= 65536);

    // 1) dots (+ trailing zero-fill)
    if (fast) {
        cudaFuncSetAttribute(dots_async_kernel,
                             cudaFuncAttributeMaxDynamicSharedMemorySize,
                             DOTS_SMEM);
        int sm_count = 0;
        cudaDeviceGetAttribute(&sm_count, cudaDevAttrMultiProcessorCount, 0);
        if (sm_count <= 0) sm_count = 148;
        int max_blk = 0;
        cudaOccupancyMaxActiveBlocksPerMultiprocessor(
            &max_blk, dots_async_kernel, THREADS, DOTS_SMEM);
        if (max_blk <= 0) max_blk = 2;
        int nblocks = sm_count * max_blk;
        dots_async_kernel<<<nblocks, THREADS, DOTS_SMEM>>>(
            hr, tail, W, bias, B, E, out, BE, total, nblocks);
    } else {
        int rows = B + E;
        long long lanes = (long long)rows * 32;
        long long extra = (total > BE) ? (total - BE) : 0;
        if (extra > lanes) lanes = extra;
        int blocks = (int)((lanes + THREADS - 1) / THREADS);
        dots_kernel<<<blocks, THREADS>>>(hr, tail, W, bias, B, E, C,
                                         out, BE, total);
    }

    // 2) broadcast sum -> out (PDL, frozen config)
    if ((E & 3) == 0) {
        int E4 = E >> 2;
        dim3 grid((E4 + THREADS - 1) / THREADS, (B + BTILE - 1) / BTILE);

        cudaLaunchConfig_t cfg = {};
        cfg.gridDim  = grid;
        cfg.blockDim = dim3(THREADS, 1, 1);
        cfg.dynamicSmemBytes = 0;
        cudaLaunchAttribute attrs[1];
        attrs[0].id = cudaLaunchAttributeProgrammaticStreamSerialization;
        attrs[0].val.programmaticStreamSerializationAllowed = 1;
        cfg.attrs = attrs;
        cfg.numAttrs = 1;

        cudaLaunchKernelEx(&cfg, bcast_vec_kernel,
                           out, E4, (long long)E, B);
    } else {
        dim3 grid((E + THREADS - 1) / THREADS, B);
        bcast_scalar_kernel<<<grid, THREADS>>>(out, E);
    }
}